// round 11
// baseline (speedup 1.0000x reference)
#include <cuda_runtime.h>
#include <cuda_fp16.h>
#include <math.h>
#include <stdint.h>

// ---------------------------------------------------------------------------
// AngleLinear (SphereFace A-Softmax forward, m=4, it=1) — mma.sync fp16
//   out[n,c] = clip( (x_n . w_c) / (|x_n| |w_c|), -1, 1 ) * |x_n|
//   out[n, target[n]] += (phi(c_t) - c_t) * |x_n| / (1 + lambda)
// R11: BK=32, 4-stage cp.async (wait_group 2), 2 CTAs x 256 thr / SM.
// wtrans: 1 block per 64-col stripe loops all d-tiles (no atomics/zero pass).
// xprep: fused x fp16-convert + row norms.
// ---------------------------------------------------------------------------

#define PI_F 3.141592653f
#define INVL ((float)(1.0 / (1.0 + 1500.0 / 1.1)))

#define CMAX 100352
#define DMAX 512
#define NMAX 512

__device__ float g_wnorm2[CMAX];   // per-column sum of squares
__device__ float g_xnorm[NMAX];
__device__ __half g_Wh[(size_t)CMAX * DMAX];  // W^T [c][d], fp16
__device__ __half g_Ah[(size_t)NMAX * DMAX];  // x [n][d], fp16

// ---------------- PTX helpers (all sm_80-safe) ----------------
__device__ __forceinline__ uint32_t smem_u32(const void* p) {
    uint32_t a;
    asm("{ .reg .u64 t; cvta.to.shared.u64 t, %1; cvt.u32.u64 %0, t; }"
        : "=r"(a) : "l"(p));
    return a;
}
__device__ __forceinline__ void cp16(uint32_t dst, const void* src) {
    asm volatile("cp.async.cg.shared.global [%0], [%1], 16;"
                 :: "r"(dst), "l"(src));
}
#define CP_COMMIT() asm volatile("cp.async.commit_group;" ::: "memory")
#define CP_WAIT2() asm volatile("cp.async.wait_group 2;" ::: "memory")

__device__ __forceinline__ void ldsm4(uint32_t& r0, uint32_t& r1, uint32_t& r2,
                                      uint32_t& r3, uint32_t addr) {
    asm volatile("ldmatrix.sync.aligned.m8n8.x4.shared.b16 {%0,%1,%2,%3}, [%4];"
                 : "=r"(r0), "=r"(r1), "=r"(r2), "=r"(r3) : "r"(addr));
}
__device__ __forceinline__ void mma16816(float* c, const uint32_t* a,
                                         uint32_t b0, uint32_t b1) {
    asm volatile(
        "mma.sync.aligned.m16n8k16.row.col.f32.f16.f16.f32 "
        "{%0,%1,%2,%3}, {%4,%5,%6,%7}, {%8,%9}, {%0,%1,%2,%3};"
        : "+f"(c[0]), "+f"(c[1]), "+f"(c[2]), "+f"(c[3])
        : "r"(a[0]), "r"(a[1]), "r"(a[2]), "r"(a[3]), "r"(b0), "r"(b1));
}

// ---------------- pre-pass kernels ----------------
// x [N,D] f32 -> fp16 + row norm. One block (128 thr) per row.
__global__ void xprep_kernel(const float* __restrict__ X, int D) {
    __shared__ float red[4];
    const int r = blockIdx.x;
    const int tid = threadIdx.x;
    const float4 v = *reinterpret_cast<const float4*>(X + (size_t)r * D + tid * 4);
    __half2 h0 = __floats2half2_rn(v.x, v.y);
    __half2 h1 = __floats2half2_rn(v.z, v.w);
    uint2 u;
    u.x = *reinterpret_cast<const uint32_t*>(&h0);
    u.y = *reinterpret_cast<const uint32_t*>(&h1);
    *reinterpret_cast<uint2*>(&g_Ah[(size_t)r * D + tid * 4]) = u;
    float s = fmaf(v.x, v.x, fmaf(v.y, v.y, fmaf(v.z, v.z, v.w * v.w)));
#pragma unroll
    for (int o = 16; o > 0; o >>= 1) s += __shfl_down_sync(0xffffffffu, s, o);
    if ((tid & 31) == 0) red[tid >> 5] = s;
    __syncthreads();
    if (tid == 0)
        g_xnorm[r] = sqrtf((red[0] + red[1]) + (red[2] + red[3]));
}

// W [D,C] f32 -> W^T [C,D] fp16, one block per 64-column stripe, loops over
// all d-tiles; per-column sum of squares accumulated in registers.
__global__ void wtrans_kernel(const float* __restrict__ W, int D, int C) {
    __shared__ float s[64][65];
    __shared__ float sq[4][64];
    const int tid = threadIdx.x;
    const int c0 = blockIdx.x * 64;
    const int cr = tid & 63;        // read-phase column (fixed per thread)
    const int dr = tid >> 6;        // read-phase row base (0..3)
    const int gc_r = c0 + cr;
    float acc = 0.0f;

    for (int d0 = 0; d0 < D; d0 += 64) {
#pragma unroll
        for (int i = 0; i < 16; i++) {
            int d = dr + 4 * i;
            float v = (gc_r < C) ? W[(size_t)(d0 + d) * C + gc_r] : 0.0f;
            s[d][cr] = v;
            acc = fmaf(v, v, acc);
        }
        __syncthreads();
#pragma unroll
        for (int i = 0; i < 8; i++) {
            int e = tid + 256 * i;
            int c = e >> 5;              // 0..63
            int dp = (e & 31) * 2;       // even d
            int gc = c0 + c;
            if (gc < C) {
                __half2 h = __floats2half2_rn(s[dp][c], s[dp + 1][c]);
                *reinterpret_cast<__half2*>(&g_Wh[(size_t)gc * D + d0 + dp]) = h;
            }
        }
        __syncthreads();
    }
    sq[dr][cr] = acc;
    __syncthreads();
    if (tid < 64 && c0 + tid < C)
        g_wnorm2[c0 + tid] = (sq[0][tid] + sq[1][tid]) + (sq[2][tid] + sq[3][tid]);
}

// ---------------- epilogue math ----------------
__device__ __forceinline__ float epi_elem(float v, float rxn, float xn,
                                          float rwn, int c, long long tgt) {
    float cc = v * rxn * rwn;
    cc = fminf(1.0f, fmaxf(-1.0f, cc));
    float o = cc * xn;
    if ((long long)c == tgt) {
        float c2 = cc * cc;
        float cosm = fmaf(8.0f * c2, c2, fmaf(-8.0f, c2, 1.0f));
        float th = acosf(cc);
        float kf = floorf(th * (4.0f / PI_F));
        int ki = (int)kf;
        float sgn = (ki & 1) ? -1.0f : 1.0f;
        float phi = fmaf(sgn, cosm, -2.0f * kf);
        o += (phi - cc) * xn * INVL;
    }
    return o;
}

// ---------------- mma.sync GEMM + epilogue ----------------
// BM=128, BN=128, BK=32. 256 threads = 8 warps (4x2), warp tile 32x64.
// 2 CTAs/SM. Pitch 80 (conflict-free ldmatrix). 4-stage cp.async, wait_group 2,
// 1 syncthreads per iter.
#define BM 128
#define BN 128
#define BK 32
#define PA 80
#define TILE_B (128 * PA)           // 10240 per tile (A or B)
#define STAGE_B (2 * TILE_B)        // 20480 per stage
#define STAGES 4
#define SM_TOTAL (STAGES * STAGE_B) // 81920 -> 2 CTAs/SM (160KB)

#define OFF_A 0
#define OFF_B TILE_B

__device__ __forceinline__ void load_stage(uint32_t base, int m0, int c0,
                                           int it, int D, int tid) {
    const int r = tid >> 1;               // 0..127
    const int ch = (tid & 1) * 2;         // chunks {0,1} or {2,3}
#pragma unroll
    for (int q = 0; q < 2; q++) {
        const uint32_t doff = (uint32_t)(r * PA + (ch + q) * 16);
        const size_t koff = (size_t)it * BK + (ch + q) * 8;
        cp16(base + OFF_A + doff, g_Ah + (size_t)(m0 + r) * D + koff);
        cp16(base + OFF_B + doff, g_Wh + (size_t)(c0 + r) * D + koff);
    }
}

__global__ void __launch_bounds__(256, 2)
gemm_epi_kernel(const long long* __restrict__ TGT, float* __restrict__ OUT,
                int N, int D, int C) {
    extern __shared__ char smem[];
    const uint32_t sb = smem_u32(smem);
    const int tid = threadIdx.x;
    const int wid = tid >> 5;
    const int l = tid & 31;
    const int wm = wid >> 1;         // 0..3 -> rows 32*wm
    const int wn = wid & 1;          // 0..1 -> cols 64*wn
    const int m0 = blockIdx.x * BM;  // x fastest: m-tiles share W tile in L2
    const int c0 = blockIdx.y * BN;

    // A ldmatrix (normal): rows 32wm + l%16, 16B col select by l/16
    const uint32_t a_off =
        (uint32_t)((32 * wm + (l & 15)) * PA + (l >> 4) * 16);
    // B ldmatrix (K-major): rows 64wn + l%8 + 8*(l/16), 16B col by (l>>3)&1
    const uint32_t b_off =
        (uint32_t)((64 * wn + (l & 7) + ((l >> 4) << 3)) * PA +
                   ((l >> 3) & 1) * 16);

    float acc[2][8][4];
#pragma unroll
    for (int i = 0; i < 2; i++)
#pragma unroll
        for (int j = 0; j < 8; j++)
#pragma unroll
            for (int q = 0; q < 4; q++) acc[i][j][q] = 0.0f;

    const int iters = D / BK;  // 16
    load_stage(sb, m0, c0, 0, D, tid);
    CP_COMMIT();
    load_stage(sb + STAGE_B, m0, c0, 1, D, tid);
    CP_COMMIT();
    load_stage(sb + 2 * STAGE_B, m0, c0, 2, D, tid);
    CP_COMMIT();

    for (int it = 0; it < iters; it++) {
        CP_WAIT2();          // stage it resident; it+1, it+2 may be in flight
        __syncthreads();     // stage (it+3)%4 = (it-1)%4: readers done
        if (it + 3 < iters)
            load_stage(sb + (uint32_t)((it + 3) % STAGES) * STAGE_B,
                       m0, c0, it + 3, D, tid);
        CP_COMMIT();

        const uint32_t base = sb + (uint32_t)(it % STAGES) * STAGE_B;
#pragma unroll
        for (int ks = 0; ks < 2; ks++) {
            const uint32_t ko = (uint32_t)(ks * 32);
            uint32_t ah[2][4];
            ldsm4(ah[0][0], ah[0][1], ah[0][2], ah[0][3],
                  base + OFF_A + a_off + ko);
            ldsm4(ah[1][0], ah[1][1], ah[1][2], ah[1][3],
                  base + OFF_A + a_off + ko + 16 * PA);

            uint32_t bh[8][2];
#pragma unroll
            for (int g = 0; g < 4; g++)
                ldsm4(bh[2 * g][0], bh[2 * g][1], bh[2 * g + 1][0],
                      bh[2 * g + 1][1],
                      base + OFF_B + b_off + ko + (uint32_t)g * (16 * PA));

#pragma unroll
            for (int i = 0; i < 2; i++)
#pragma unroll
                for (int j = 0; j < 8; j++)
                    mma16816(acc[i][j], ah[i], bh[j][0], bh[j][1]);
        }
    }

    // ---- epilogue ----
    const int base_m = m0 + 32 * wm + (l >> 2);
    float xns[2][2], rxns[2][2];
    long long tgs[2][2];
#pragma unroll
    for (int i = 0; i < 2; i++)
#pragma unroll
        for (int p = 0; p < 2; p++) {
            int row = base_m + 16 * i + 8 * p;  // always < N (N=512, BM exact)
            float xn = g_xnorm[row];
            xns[i][p] = xn;
            rxns[i][p] = 1.0f / xn;
            tgs[i][p] = TGT[row];
        }

#pragma unroll
    for (int j = 0; j < 8; j++) {
        const int c = c0 + 64 * wn + 8 * j + 2 * (l & 3);
        if (c >= C) continue;  // C even -> pair fully valid or fully out
        const float rw0 = rsqrtf(g_wnorm2[c]);
        const float rw1 = rsqrtf(g_wnorm2[c + 1]);
#pragma unroll
        for (int i = 0; i < 2; i++)
#pragma unroll
            for (int p = 0; p < 2; p++) {
                const int row = base_m + 16 * i + 8 * p;
                float2 o;
                o.x = epi_elem(acc[i][j][2 * p + 0], rxns[i][p], xns[i][p],
                               rw0, c, tgs[i][p]);
                o.y = epi_elem(acc[i][j][2 * p + 1], rxns[i][p], xns[i][p],
                               rw1, c + 1, tgs[i][p]);
                *reinterpret_cast<float2*>(&OUT[(size_t)row * C + c]) = o;
            }
    }
}

// ---------------------------------------------------------------------------
extern "C" void kernel_launch(void* const* d_in, const int* in_sizes, int n_in,
                              void* d_out, int out_size) {
    const float* x = (const float*)d_in[0];
    const long long* tgt = (const long long*)d_in[1];
    const float* w = (const float*)d_in[2];
    float* out = (float*)d_out;

    const int N = in_sizes[1];            // 512
    const int D = in_sizes[0] / N;        // 512
    const int C = in_sizes[2] / D;        // 100000

    xprep_kernel<<<N, 128>>>(x, D);
    wtrans_kernel<<<(C + 63) / 64, 256>>>(w, D, C);

    cudaFuncSetAttribute(gemm_epi_kernel,
                         cudaFuncAttributeMaxDynamicSharedMemorySize, SM_TOTAL);
    dim3 grid((N + BM - 1) / BM, (C + BN - 1) / BN);
    gemm_epi_kernel<<<grid, 256, SM_TOTAL>>>(tgt, out, N, D, C);
}

// round 12
// speedup vs baseline: 1.2192x; 1.2192x over previous
#include <cuda_runtime.h>
#include <cuda_fp16.h>
#include <math.h>
#include <stdint.h>

// ---------------------------------------------------------------------------
// AngleLinear (SphereFace A-Softmax forward, m=4, it=1) — mma.sync fp16
//   out[n,c] = clip( (x_n . w_c) / (|x_n| |w_c|), -1, 1 ) * |x_n|
//   out[n, target[n]] += (phi(c_t) - c_t) * |x_n| / (1 + lambda)
// R12: compose best-measured components:
//   GEMM  = R9  (BK=32, 3-stage cp.async, wait_group 1, 2 CTAs x 256 thr)
//   wtrans= R10 (block per 64x64 tile, reg-folded norms, half2 writes, atomics)
//   xprep = R11 (fused x fp16 convert + row norm)
// ---------------------------------------------------------------------------

#define PI_F 3.141592653f
#define INVL ((float)(1.0 / (1.0 + 1500.0 / 1.1)))

#define CMAX 100352
#define DMAX 512
#define NMAX 512

__device__ float g_wnorm2[CMAX];   // per-column sum of squares (atomic-folded)
__device__ float g_xnorm[NMAX];
__device__ __half g_Wh[(size_t)CMAX * DMAX];  // W^T [c][d], fp16
__device__ __half g_Ah[(size_t)NMAX * DMAX];  // x [n][d], fp16

// ---------------- PTX helpers (all sm_80-safe) ----------------
__device__ __forceinline__ uint32_t smem_u32(const void* p) {
    uint32_t a;
    asm("{ .reg .u64 t; cvta.to.shared.u64 t, %1; cvt.u32.u64 %0, t; }"
        : "=r"(a) : "l"(p));
    return a;
}
__device__ __forceinline__ void cp16(uint32_t dst, const void* src) {
    asm volatile("cp.async.cg.shared.global [%0], [%1], 16;"
                 :: "r"(dst), "l"(src));
}
#define CP_COMMIT() asm volatile("cp.async.commit_group;" ::: "memory")
#define CP_WAIT1() asm volatile("cp.async.wait_group 1;" ::: "memory")

__device__ __forceinline__ void ldsm4(uint32_t& r0, uint32_t& r1, uint32_t& r2,
                                      uint32_t& r3, uint32_t addr) {
    asm volatile("ldmatrix.sync.aligned.m8n8.x4.shared.b16 {%0,%1,%2,%3}, [%4];"
                 : "=r"(r0), "=r"(r1), "=r"(r2), "=r"(r3) : "r"(addr));
}
__device__ __forceinline__ void mma16816(float* c, const uint32_t* a,
                                         uint32_t b0, uint32_t b1) {
    asm volatile(
        "mma.sync.aligned.m16n8k16.row.col.f32.f16.f16.f32 "
        "{%0,%1,%2,%3}, {%4,%5,%6,%7}, {%8,%9}, {%0,%1,%2,%3};"
        : "+f"(c[0]), "+f"(c[1]), "+f"(c[2]), "+f"(c[3])
        : "r"(a[0]), "r"(a[1]), "r"(a[2]), "r"(a[3]), "r"(b0), "r"(b1));
}

// ---------------- pre-pass kernels ----------------
__global__ void zero_kernel() {
    int i = blockIdx.x * blockDim.x + threadIdx.x;
    if (i < CMAX) g_wnorm2[i] = 0.0f;
}

// x [N,D] f32 -> fp16 + row norm. One block (128 thr) per row.
__global__ void xprep_kernel(const float* __restrict__ X, int D) {
    __shared__ float red[4];
    const int r = blockIdx.x;
    const int tid = threadIdx.x;
    const float4 v = *reinterpret_cast<const float4*>(X + (size_t)r * D + tid * 4);
    __half2 h0 = __floats2half2_rn(v.x, v.y);
    __half2 h1 = __floats2half2_rn(v.z, v.w);
    uint2 u;
    u.x = *reinterpret_cast<const uint32_t*>(&h0);
    u.y = *reinterpret_cast<const uint32_t*>(&h1);
    *reinterpret_cast<uint2*>(&g_Ah[(size_t)r * D + tid * 4]) = u;
    float s = fmaf(v.x, v.x, fmaf(v.y, v.y, fmaf(v.z, v.z, v.w * v.w)));
#pragma unroll
    for (int o = 16; o > 0; o >>= 1) s += __shfl_down_sync(0xffffffffu, s, o);
    if ((tid & 31) == 0) red[tid >> 5] = s;
    __syncthreads();
    if (tid == 0)
        g_xnorm[r] = sqrtf((red[0] + red[1]) + (red[2] + red[3]));
}

// W [D,C] f32 -> W^T [C,D] fp16 (64x64 tiles through SMEM).
// Column sum-of-squares folded into the read phase (register acc),
// half2-vectorized write phase. (R10 verbatim — measured 49 us, at LTS cap.)
__global__ void wtrans_kernel(const float* __restrict__ W, int D, int C) {
    __shared__ float s[64][65];
    __shared__ float sq[4][64];
    const int tid = threadIdx.x;
    const int c0 = blockIdx.x * 64;
    const int d0 = blockIdx.y * 64;

    const int cr = tid & 63;        // read-phase column (fixed per thread)
    const int dr = tid >> 6;        // read-phase row base (0..3)
    const int gc_r = c0 + cr;
    float acc = 0.0f;
#pragma unroll
    for (int i = 0; i < 16; i++) {
        int d = dr + 4 * i;
        float v = (gc_r < C) ? W[(size_t)(d0 + d) * C + gc_r] : 0.0f;
        s[d][cr] = v;
        acc = fmaf(v, v, acc);
    }
    sq[dr][cr] = acc;
    __syncthreads();

#pragma unroll
    for (int i = 0; i < 8; i++) {
        int e = tid + 256 * i;
        int c = e >> 5;              // 0..63
        int dp = (e & 31) * 2;       // even d
        int gc = c0 + c;
        if (gc < C) {
            __half2 h = __floats2half2_rn(s[dp][c], s[dp + 1][c]);
            *reinterpret_cast<__half2*>(&g_Wh[(size_t)gc * D + d0 + dp]) = h;
        }
    }
    if (tid < 64 && c0 + tid < C) {
        float t = (sq[0][tid] + sq[1][tid]) + (sq[2][tid] + sq[3][tid]);
        atomicAdd(&g_wnorm2[c0 + tid], t);
    }
}

// ---------------- epilogue math ----------------
__device__ __forceinline__ float epi_elem(float v, float rxn, float xn,
                                          float rwn, int c, long long tgt) {
    float cc = v * rxn * rwn;
    cc = fminf(1.0f, fmaxf(-1.0f, cc));
    float o = cc * xn;
    if ((long long)c == tgt) {
        float c2 = cc * cc;
        float cosm = fmaf(8.0f * c2, c2, fmaf(-8.0f, c2, 1.0f));
        float th = acosf(cc);
        float kf = floorf(th * (4.0f / PI_F));
        int ki = (int)kf;
        float sgn = (ki & 1) ? -1.0f : 1.0f;
        float phi = fmaf(sgn, cosm, -2.0f * kf);
        o += (phi - cc) * xn * INVL;
    }
    return o;
}

// ---------------- mma.sync GEMM + epilogue (R9 verbatim) ----------------
// BM=128, BN=128, BK=32. 256 threads = 8 warps (4x2), warp tile 32x64.
// 2 CTAs/SM. Pitch 80 (conflict-free ldmatrix). 3-stage cp.async,
// wait_group 1, 1 syncthreads per iter.
#define BM 128
#define BN 128
#define BK 32
#define PA 80
#define TILE_B (128 * PA)           // 10240 per tile (A or B)
#define STAGE_B (2 * TILE_B)        // 20480 per stage
#define STAGES 3
#define SM_TOTAL (STAGES * STAGE_B) // 61440 -> 2 CTAs/SM

#define OFF_A 0
#define OFF_B TILE_B

__device__ __forceinline__ void load_stage(uint32_t base, int m0, int c0,
                                           int it, int D, int tid) {
    const int r = tid >> 1;               // 0..127
    const int ch = (tid & 1) * 2;         // chunks {0,1} or {2,3}
#pragma unroll
    for (int q = 0; q < 2; q++) {
        const uint32_t doff = (uint32_t)(r * PA + (ch + q) * 16);
        const size_t koff = (size_t)it * BK + (ch + q) * 8;
        cp16(base + OFF_A + doff, g_Ah + (size_t)(m0 + r) * D + koff);
        cp16(base + OFF_B + doff, g_Wh + (size_t)(c0 + r) * D + koff);
    }
}

__global__ void __launch_bounds__(256, 2)
gemm_epi_kernel(const long long* __restrict__ TGT, float* __restrict__ OUT,
                int N, int D, int C) {
    extern __shared__ char smem[];
    const uint32_t sb = smem_u32(smem);
    const int tid = threadIdx.x;
    const int wid = tid >> 5;
    const int l = tid & 31;
    const int wm = wid >> 1;         // 0..3 -> rows 32*wm
    const int wn = wid & 1;          // 0..1 -> cols 64*wn
    const int m0 = blockIdx.x * BM;  // x fastest: m-tiles share W tile in L2
    const int c0 = blockIdx.y * BN;

    // A ldmatrix (normal): rows 32wm + l%16, 16B col select by l/16
    const uint32_t a_off =
        (uint32_t)((32 * wm + (l & 15)) * PA + (l >> 4) * 16);
    // B ldmatrix (K-major): rows 64wn + l%8 + 8*(l/16), 16B col by (l>>3)&1
    const uint32_t b_off =
        (uint32_t)((64 * wn + (l & 7) + ((l >> 4) << 3)) * PA +
                   ((l >> 3) & 1) * 16);

    float acc[2][8][4];
#pragma unroll
    for (int i = 0; i < 2; i++)
#pragma unroll
        for (int j = 0; j < 8; j++)
#pragma unroll
            for (int q = 0; q < 4; q++) acc[i][j][q] = 0.0f;

    const int iters = D / BK;  // 16
    load_stage(sb, m0, c0, 0, D, tid);
    CP_COMMIT();
    load_stage(sb + STAGE_B, m0, c0, 1, D, tid);
    CP_COMMIT();

    for (int it = 0; it < iters; it++) {
        CP_WAIT1();          // stage it resident
        __syncthreads();     // stage (it+2)%3 free of readers
        if (it + 2 < iters)
            load_stage(sb + (uint32_t)((it + 2) % STAGES) * STAGE_B,
                       m0, c0, it + 2, D, tid);
        CP_COMMIT();

        const uint32_t base = sb + (uint32_t)(it % STAGES) * STAGE_B;
#pragma unroll
        for (int ks = 0; ks < 2; ks++) {
            const uint32_t ko = (uint32_t)(ks * 32);
            uint32_t ah[2][4];
            ldsm4(ah[0][0], ah[0][1], ah[0][2], ah[0][3],
                  base + OFF_A + a_off + ko);
            ldsm4(ah[1][0], ah[1][1], ah[1][2], ah[1][3],
                  base + OFF_A + a_off + ko + 16 * PA);

            uint32_t bh[8][2];
#pragma unroll
            for (int g = 0; g < 4; g++)
                ldsm4(bh[2 * g][0], bh[2 * g][1], bh[2 * g + 1][0],
                      bh[2 * g + 1][1],
                      base + OFF_B + b_off + ko + (uint32_t)g * (16 * PA));

#pragma unroll
            for (int i = 0; i < 2; i++)
#pragma unroll
                for (int j = 0; j < 8; j++)
                    mma16816(acc[i][j], ah[i], bh[j][0], bh[j][1]);
        }
    }

    // ---- epilogue ----
    const int base_m = m0 + 32 * wm + (l >> 2);
    float xns[2][2], rxns[2][2];
    long long tgs[2][2];
#pragma unroll
    for (int i = 0; i < 2; i++)
#pragma unroll
        for (int p = 0; p < 2; p++) {
            int row = base_m + 16 * i + 8 * p;  // always < N (N=512, BM exact)
            float xn = g_xnorm[row];
            xns[i][p] = xn;
            rxns[i][p] = 1.0f / xn;
            tgs[i][p] = TGT[row];
        }

#pragma unroll
    for (int j = 0; j < 8; j++) {
        const int c = c0 + 64 * wn + 8 * j + 2 * (l & 3);
        if (c >= C) continue;  // C even -> pair fully valid or fully out
        const float rw0 = rsqrtf(g_wnorm2[c]);
        const float rw1 = rsqrtf(g_wnorm2[c + 1]);
#pragma unroll
        for (int i = 0; i < 2; i++)
#pragma unroll
            for (int p = 0; p < 2; p++) {
                const int row = base_m + 16 * i + 8 * p;
                float2 o;
                o.x = epi_elem(acc[i][j][2 * p + 0], rxns[i][p], xns[i][p],
                               rw0, c, tgs[i][p]);
                o.y = epi_elem(acc[i][j][2 * p + 1], rxns[i][p], xns[i][p],
                               rw1, c + 1, tgs[i][p]);
                *reinterpret_cast<float2*>(&OUT[(size_t)row * C + c]) = o;
            }
    }
}

// ---------------------------------------------------------------------------
extern "C" void kernel_launch(void* const* d_in, const int* in_sizes, int n_in,
                              void* d_out, int out_size) {
    const float* x = (const float*)d_in[0];
    const long long* tgt = (const long long*)d_in[1];
    const float* w = (const float*)d_in[2];
    float* out = (float*)d_out;

    const int N = in_sizes[1];            // 512
    const int D = in_sizes[0] / N;        // 512
    const int C = in_sizes[2] / D;        // 100000

    zero_kernel<<<(CMAX + 255) / 256, 256>>>();
    xprep_kernel<<<N, 128>>>(x, D);
    {
        dim3 tg2((C + 63) / 64, (D + 63) / 64);
        wtrans_kernel<<<tg2, 256>>>(w, D, C);
    }

    cudaFuncSetAttribute(gemm_epi_kernel,
                         cudaFuncAttributeMaxDynamicSharedMemorySize, SM_TOTAL);
    dim3 grid((N + BM - 1) / BM, (C + BN - 1) / BN);
    gemm_epi_kernel<<<grid, 256, SM_TOTAL>>>(tgt, out, N, D, C);
}

// round 13
// speedup vs baseline: 1.2363x; 1.0140x over previous
#include <cuda_runtime.h>
#include <cuda_fp16.h>
#include <math.h>
#include <stdint.h>

// ---------------------------------------------------------------------------
// AngleLinear (SphereFace A-Softmax forward, m=4, it=1) — mma.sync fp16
//   out[n,c] = clip( (x_n . w_c) / (|x_n| |w_c|), -1, 1 ) * |x_n|
//   out[n, target[n]] += (phi(c_t) - c_t) * |x_n| / (1 + lambda)
// R13: occupancy push. CTA tile 128x64, warp tile 32x32 (acc=32 regs),
// 3 CTAs x 256 thr per SM (24 warps/SM vs 16). Same 3-stage cp.async pipeline.
// ---------------------------------------------------------------------------

#define PI_F 3.141592653f
#define INVL ((float)(1.0 / (1.0 + 1500.0 / 1.1)))

#define CMAX 100352
#define DMAX 512
#define NMAX 512

__device__ float g_wnorm2[CMAX];   // per-column sum of squares (atomic-folded)
__device__ float g_xnorm[NMAX];
__device__ __half g_Wh[(size_t)CMAX * DMAX];  // W^T [c][d], fp16
__device__ __half g_Ah[(size_t)NMAX * DMAX];  // x [n][d], fp16

// ---------------- PTX helpers (all sm_80-safe) ----------------
__device__ __forceinline__ uint32_t smem_u32(const void* p) {
    uint32_t a;
    asm("{ .reg .u64 t; cvta.to.shared.u64 t, %1; cvt.u32.u64 %0, t; }"
        : "=r"(a) : "l"(p));
    return a;
}
__device__ __forceinline__ void cp16(uint32_t dst, const void* src) {
    asm volatile("cp.async.cg.shared.global [%0], [%1], 16;"
                 :: "r"(dst), "l"(src));
}
#define CP_COMMIT() asm volatile("cp.async.commit_group;" ::: "memory")
#define CP_WAIT1() asm volatile("cp.async.wait_group 1;" ::: "memory")

__device__ __forceinline__ void ldsm4(uint32_t& r0, uint32_t& r1, uint32_t& r2,
                                      uint32_t& r3, uint32_t addr) {
    asm volatile("ldmatrix.sync.aligned.m8n8.x4.shared.b16 {%0,%1,%2,%3}, [%4];"
                 : "=r"(r0), "=r"(r1), "=r"(r2), "=r"(r3) : "r"(addr));
}
__device__ __forceinline__ void mma16816(float* c, const uint32_t* a,
                                         uint32_t b0, uint32_t b1) {
    asm volatile(
        "mma.sync.aligned.m16n8k16.row.col.f32.f16.f16.f32 "
        "{%0,%1,%2,%3}, {%4,%5,%6,%7}, {%8,%9}, {%0,%1,%2,%3};"
        : "+f"(c[0]), "+f"(c[1]), "+f"(c[2]), "+f"(c[3])
        : "r"(a[0]), "r"(a[1]), "r"(a[2]), "r"(a[3]), "r"(b0), "r"(b1));
}

// ---------------- pre-pass kernels ----------------
__global__ void zero_kernel() {
    int i = blockIdx.x * blockDim.x + threadIdx.x;
    if (i < CMAX) g_wnorm2[i] = 0.0f;
}

// x [N,D] f32 -> fp16 + row norm. One block (128 thr) per row.
__global__ void xprep_kernel(const float* __restrict__ X, int D) {
    __shared__ float red[4];
    const int r = blockIdx.x;
    const int tid = threadIdx.x;
    const float4 v = *reinterpret_cast<const float4*>(X + (size_t)r * D + tid * 4);
    __half2 h0 = __floats2half2_rn(v.x, v.y);
    __half2 h1 = __floats2half2_rn(v.z, v.w);
    uint2 u;
    u.x = *reinterpret_cast<const uint32_t*>(&h0);
    u.y = *reinterpret_cast<const uint32_t*>(&h1);
    *reinterpret_cast<uint2*>(&g_Ah[(size_t)r * D + tid * 4]) = u;
    float s = fmaf(v.x, v.x, fmaf(v.y, v.y, fmaf(v.z, v.z, v.w * v.w)));
#pragma unroll
    for (int o = 16; o > 0; o >>= 1) s += __shfl_down_sync(0xffffffffu, s, o);
    if ((tid & 31) == 0) red[tid >> 5] = s;
    __syncthreads();
    if (tid == 0)
        g_xnorm[r] = sqrtf((red[0] + red[1]) + (red[2] + red[3]));
}

// W [D,C] f32 -> W^T [C,D] fp16 (64x64 tiles through SMEM).
// Column sum-of-squares folded into the read phase; half2 writes.
// (R10 verbatim — measured 49 us, at LTS cap.)
__global__ void wtrans_kernel(const float* __restrict__ W, int D, int C) {
    __shared__ float s[64][65];
    __shared__ float sq[4][64];
    const int tid = threadIdx.x;
    const int c0 = blockIdx.x * 64;
    const int d0 = blockIdx.y * 64;

    const int cr = tid & 63;
    const int dr = tid >> 6;
    const int gc_r = c0 + cr;
    float acc = 0.0f;
#pragma unroll
    for (int i = 0; i < 16; i++) {
        int d = dr + 4 * i;
        float v = (gc_r < C) ? W[(size_t)(d0 + d) * C + gc_r] : 0.0f;
        s[d][cr] = v;
        acc = fmaf(v, v, acc);
    }
    sq[dr][cr] = acc;
    __syncthreads();

#pragma unroll
    for (int i = 0; i < 8; i++) {
        int e = tid + 256 * i;
        int c = e >> 5;
        int dp = (e & 31) * 2;
        int gc = c0 + c;
        if (gc < C) {
            __half2 h = __floats2half2_rn(s[dp][c], s[dp + 1][c]);
            *reinterpret_cast<__half2*>(&g_Wh[(size_t)gc * D + d0 + dp]) = h;
        }
    }
    if (tid < 64 && c0 + tid < C) {
        float t = (sq[0][tid] + sq[1][tid]) + (sq[2][tid] + sq[3][tid]);
        atomicAdd(&g_wnorm2[c0 + tid], t);
    }
}

// ---------------- epilogue math ----------------
__device__ __forceinline__ float epi_elem(float v, float rxn, float xn,
                                          float rwn, int c, long long tgt) {
    float cc = v * rxn * rwn;
    cc = fminf(1.0f, fmaxf(-1.0f, cc));
    float o = cc * xn;
    if ((long long)c == tgt) {
        float c2 = cc * cc;
        float cosm = fmaf(8.0f * c2, c2, fmaf(-8.0f, c2, 1.0f));
        float th = acosf(cc);
        float kf = floorf(th * (4.0f / PI_F));
        int ki = (int)kf;
        float sgn = (ki & 1) ? -1.0f : 1.0f;
        float phi = fmaf(sgn, cosm, -2.0f * kf);
        o += (phi - cc) * xn * INVL;
    }
    return o;
}

// ---------------- mma.sync GEMM + epilogue ----------------
// BM=128, BN=64, BK=32. 256 threads = 8 warps (4x2), warp tile 32x32.
// 3 CTAs/SM (24 warps). Pitch 80 (conflict-free ldmatrix). 3-stage cp.async,
// wait_group 1, 1 syncthreads per iter.
#define BM 128
#define BN 64
#define BK 32
#define PA 80
#define OFF_A 0
#define OFF_B (BM * PA)                   // 10240
#define STAGE_B (OFF_B + BN * PA)         // 15360 per stage
#define STAGES 3
#define SM_TOTAL (STAGES * STAGE_B)       // 46080 -> 3 CTAs/SM (135KB)

__device__ __forceinline__ void load_stage(uint32_t base, int m0, int c0,
                                           int it, int D, int tid) {
    // A: 128 rows x 4 chunks -> 2 per thread
    {
        const int r = tid >> 1;
        const int ch = (tid & 1) * 2;
#pragma unroll
        for (int q = 0; q < 2; q++)
            cp16(base + OFF_A + (uint32_t)(r * PA + (ch + q) * 16),
                 g_Ah + (size_t)(m0 + r) * D + (size_t)it * BK + (ch + q) * 8);
    }
    // B: 64 rows x 4 chunks -> 1 per thread
    {
        const int r = tid >> 2;
        const int ch = tid & 3;
        cp16(base + OFF_B + (uint32_t)(r * PA + ch * 16),
             g_Wh + (size_t)(c0 + r) * D + (size_t)it * BK + ch * 8);
    }
}

__global__ void __launch_bounds__(256, 3)
gemm_epi_kernel(const long long* __restrict__ TGT, float* __restrict__ OUT,
                int N, int D, int C) {
    extern __shared__ char smem[];
    const uint32_t sb = smem_u32(smem);
    const int tid = threadIdx.x;
    const int wid = tid >> 5;
    const int l = tid & 31;
    const int wm = wid >> 1;         // 0..3 -> rows 32*wm
    const int wn = wid & 1;          // 0..1 -> cols 32*wn
    const int m0 = blockIdx.x * BM;  // x fastest: m-tiles share W tile in L2
    const int c0 = blockIdx.y * BN;

    // A ldmatrix (normal): rows 32wm + l%16, 16B col select by l/16
    const uint32_t a_off =
        (uint32_t)((32 * wm + (l & 15)) * PA + (l >> 4) * 16);
    // B ldmatrix (K-major): rows 32wn + l%8 + 8*(l/16), 16B col by (l>>3)&1
    const uint32_t b_off =
        (uint32_t)((32 * wn + (l & 7) + ((l >> 4) << 3)) * PA +
                   ((l >> 3) & 1) * 16);

    float acc[2][4][4];
#pragma unroll
    for (int i = 0; i < 2; i++)
#pragma unroll
        for (int j = 0; j < 4; j++)
#pragma unroll
            for (int q = 0; q < 4; q++) acc[i][j][q] = 0.0f;

    const int iters = D / BK;  // 16
    load_stage(sb, m0, c0, 0, D, tid);
    CP_COMMIT();
    load_stage(sb + STAGE_B, m0, c0, 1, D, tid);
    CP_COMMIT();

    for (int it = 0; it < iters; it++) {
        CP_WAIT1();          // stage it resident
        __syncthreads();     // stage (it+2)%3 free of readers
        if (it + 2 < iters)
            load_stage(sb + (uint32_t)((it + 2) % STAGES) * STAGE_B,
                       m0, c0, it + 2, D, tid);
        CP_COMMIT();

        const uint32_t base = sb + (uint32_t)(it % STAGES) * STAGE_B;
#pragma unroll
        for (int ks = 0; ks < 2; ks++) {
            const uint32_t ko = (uint32_t)(ks * 32);
            uint32_t ah[2][4];
            ldsm4(ah[0][0], ah[0][1], ah[0][2], ah[0][3],
                  base + OFF_A + a_off + ko);
            ldsm4(ah[1][0], ah[1][1], ah[1][2], ah[1][3],
                  base + OFF_A + a_off + ko + 16 * PA);

            uint32_t bh[4][2];
#pragma unroll
            for (int g = 0; g < 2; g++)
                ldsm4(bh[2 * g][0], bh[2 * g][1], bh[2 * g + 1][0],
                      bh[2 * g + 1][1],
                      base + OFF_B + b_off + ko + (uint32_t)g * (16 * PA));

#pragma unroll
            for (int i = 0; i < 2; i++)
#pragma unroll
                for (int j = 0; j < 4; j++)
                    mma16816(acc[i][j], ah[i], bh[j][0], bh[j][1]);
        }
    }

    // ---- epilogue ----
    const int base_m = m0 + 32 * wm + (l >> 2);
    float xns[2][2], rxns[2][2];
    long long tgs[2][2];
#pragma unroll
    for (int i = 0; i < 2; i++)
#pragma unroll
        for (int p = 0; p < 2; p++) {
            int row = base_m + 16 * i + 8 * p;  // always < N (N=512, BM exact)
            float xn = g_xnorm[row];
            xns[i][p] = xn;
            rxns[i][p] = 1.0f / xn;
            tgs[i][p] = TGT[row];
        }

#pragma unroll
    for (int j = 0; j < 4; j++) {
        const int c = c0 + 32 * wn + 8 * j + 2 * (l & 3);
        if (c >= C) continue;  // C even -> pair fully valid or fully out
        const float rw0 = rsqrtf(g_wnorm2[c]);
        const float rw1 = rsqrtf(g_wnorm2[c + 1]);
#pragma unroll
        for (int i = 0; i < 2; i++)
#pragma unroll
            for (int p = 0; p < 2; p++) {
                const int row = base_m + 16 * i + 8 * p;
                float2 o;
                o.x = epi_elem(acc[i][j][2 * p + 0], rxns[i][p], xns[i][p],
                               rw0, c, tgs[i][p]);
                o.y = epi_elem(acc[i][j][2 * p + 1], rxns[i][p], xns[i][p],
                               rw1, c + 1, tgs[i][p]);
                *reinterpret_cast<float2*>(&OUT[(size_t)row * C + c]) = o;
            }
    }
}

// ---------------------------------------------------------------------------
extern "C" void kernel_launch(void* const* d_in, const int* in_sizes, int n_in,
                              void* d_out, int out_size) {
    const float* x = (const float*)d_in[0];
    const long long* tgt = (const long long*)d_in[1];
    const float* w = (const float*)d_in[2];
    float* out = (float*)d_out;

    const int N = in_sizes[1];            // 512
    const int D = in_sizes[0] / N;        // 512
    const int C = in_sizes[2] / D;        // 100000

    zero_kernel<<<(CMAX + 255) / 256, 256>>>();
    xprep_kernel<<<N, 128>>>(x, D);
    {
        dim3 tg2((C + 63) / 64, (D + 63) / 64);
        wtrans_kernel<<<tg2, 256>>>(w, D, C);
    }

    cudaFuncSetAttribute(gemm_epi_kernel,
                         cudaFuncAttributeMaxDynamicSharedMemorySize, SM_TOTAL);
    dim3 grid((N + BM - 1) / BM, (C + BN - 1) / BN);
    gemm_epi_kernel<<<grid, 256, SM_TOTAL>>>(tgt, out, N, D, C);
}